// round 14
// baseline (speedup 1.0000x reference)
#include <cuda_runtime.h>
#include <math.h>
#include <stdint.h>
#include <mma.h>

using namespace nvcuda;

#define NP 8192
#define NB 64

__device__ float g_hi[NP * 64];   // tf32-rounded high parts, row-major [i][k]
__device__ float g_lo[NP * 64];   // tf32 low parts
__device__ float g_sq[NP];
__device__ float g_D[67108864];   // approx logits matrix (prefilter only), 256 MB

__device__ __forceinline__ unsigned fenc(float f) {
    unsigned u = __float_as_uint(f);
    return (u & 0x80000000u) ? ~u : (u | 0x80000000u);
}
__device__ __forceinline__ float fdec(unsigned k) {
    return (k & 0x80000000u) ? __uint_as_float(k ^ 0x80000000u)
                             : __uint_as_float(~k);
}

// ============================ embed (+ tf32 split) ============================
__global__ void __launch_bounds__(256, 1) k_embed(
        const float* __restrict__ X, const float* __restrict__ W,
        const float* __restrict__ b, float* __restrict__ out) {
    __shared__ float s_acc[256];
    int tid = threadIdx.x;
    int row = (blockIdx.x << 2) + (tid >> 6);
    int col = tid & 63;
    const float* xr = X + (size_t)row * 128;
    float acc = 0.f;
    #pragma unroll 16
    for (int k = 0; k < 128; ++k)
        acc = fmaf(__ldg(xr + k), __ldg(W + k * 64 + col), acc);
    acc = __fadd_rn(acc, __ldg(b + col));
    out[row * 64 + col] = acc;           // X_tilde (exact; also the recheck source)
    float hi_f;
    asm("cvt.rna.tf32.f32 %0, %1;" : "=f"(hi_f) : "f"(acc));
    float rem = __fsub_rn(acc, hi_f);
    float lo_f;
    asm("cvt.rna.tf32.f32 %0, %1;" : "=f"(lo_f) : "f"(rem));
    g_hi[row * 64 + col] = hi_f;
    g_lo[row * 64 + col] = lo_f;
    s_acc[tid] = acc;
    __syncthreads();
    if (tid < 128) {
        int sub = tid >> 5, lane = tid & 31;
        float a = s_acc[sub * 64 + lane];
        float c = s_acc[sub * 64 + 32 + lane];
        float v = a * a + c * c;
        #pragma unroll
        for (int o = 16; o; o >>= 1) v += __shfl_xor_sync(0xffffffffu, v, o);
        if (!lane) g_sq[(blockIdx.x << 2) + sub] = v;
    }
}

// ============================ wmma tf32 3-pass GEMM (prefilter logits) ============================
#define TLD 72
#define CLD 132   // multiple of 4 -> float4-aligned

struct GW {
    union {
        struct { float Ahi[128 * TLD], Alo[128 * TLD],
                       Bhi[128 * TLD], Blo[128 * TLD]; } t;   // 147.5 KB
        float sC[128 * CLD];                                  // 67.6 KB
    } u;
    float sqi[128], sqj[128];
};

__global__ void __launch_bounds__(256, 1) k_gemm_w(const float* __restrict__ tparam) {
    extern __shared__ char smraw[];
    GW& sm = *reinterpret_cast<GW*>(smraw);
    const int tid = threadIdx.x;
    const int wid = tid >> 5;

    int bidx = blockIdx.x, bi = 0;
    while (bidx >= NB - bi) { bidx -= NB - bi; ++bi; }
    const int bj = bi + bidx;
    const int I = bi * 128, J = bj * 128;
    const float scale = expf(fminf(fmaxf(tparam[0], -5.f), 5.f));

    #pragma unroll
    for (int it = 0; it < 8; ++it) {
        int f = it * 256 + tid;
        int m = f >> 4, kq = f & 15;
        int o = m * TLD + kq * 4;
        *(float4*)&sm.u.t.Ahi[o] = *(const float4*)&g_hi[(size_t)(I + m) * 64 + kq * 4];
        *(float4*)&sm.u.t.Alo[o] = *(const float4*)&g_lo[(size_t)(I + m) * 64 + kq * 4];
        *(float4*)&sm.u.t.Bhi[o] = *(const float4*)&g_hi[(size_t)(J + m) * 64 + kq * 4];
        *(float4*)&sm.u.t.Blo[o] = *(const float4*)&g_lo[(size_t)(J + m) * 64 + kq * 4];
    }
    if (tid < 128) { sm.sqi[tid] = g_sq[I + tid]; sm.sqj[tid] = g_sq[J + tid]; }
    __syncthreads();

    const int wm = (wid & 3) * 32, wn = (wid >> 2) * 64;
    wmma::fragment<wmma::accumulator, 16, 16, 8, float> c[2][4];
    #pragma unroll
    for (int s = 0; s < 2; ++s)
        #pragma unroll
        for (int t = 0; t < 4; ++t) wmma::fill_fragment(c[s][t], 0.0f);

    #pragma unroll
    for (int p = 0; p < 3; ++p) {
        const float* A = (p == 2) ? sm.u.t.Alo : sm.u.t.Ahi;
        const float* B = (p == 1) ? sm.u.t.Blo : sm.u.t.Bhi;
        #pragma unroll
        for (int k8 = 0; k8 < 8; ++k8) {
            wmma::fragment<wmma::matrix_a, 16, 16, 8, wmma::precision::tf32,
                           wmma::row_major> a[2];
            wmma::fragment<wmma::matrix_b, 16, 16, 8, wmma::precision::tf32,
                           wmma::col_major> bf[4];
            #pragma unroll
            for (int s = 0; s < 2; ++s)
                wmma::load_matrix_sync(a[s], &A[(wm + 16 * s) * TLD + k8 * 8], TLD);
            #pragma unroll
            for (int t = 0; t < 4; ++t)
                wmma::load_matrix_sync(bf[t], &B[(wn + 16 * t) * TLD + k8 * 8], TLD);
            #pragma unroll
            for (int s = 0; s < 2; ++s)
                #pragma unroll
                for (int t = 0; t < 4; ++t)
                    wmma::mma_sync(c[s][t], a[s], bf[t], c[s][t]);
        }
    }
    __syncthreads();

    #pragma unroll
    for (int s = 0; s < 2; ++s)
        #pragma unroll
        for (int t = 0; t < 4; ++t)
            wmma::store_matrix_sync(&sm.u.sC[(wm + 16 * s) * CLD + wn + 16 * t],
                                    c[s][t], CLD, wmma::mem_row_major);
    __syncthreads();

    #pragma unroll
    for (int it = 0; it < 16; ++it) {
        int f = it * 256 + tid;
        int m = f >> 5, n4 = (f & 31) * 4;
        float4 cv = *(const float4*)&sm.u.sC[m * CLD + n4];
        float si = sm.sqi[m];
        float4 sj = *(const float4*)&sm.sqj[n4];
        float4 lg;
        lg.x = __fmul_rn(fmaxf(__fadd_rn(__fadd_rn(si, sj.x), -__fmul_rn(2.0f, cv.x)), 0.f), scale);
        lg.y = __fmul_rn(fmaxf(__fadd_rn(__fadd_rn(si, sj.y), -__fmul_rn(2.0f, cv.y)), 0.f), scale);
        lg.z = __fmul_rn(fmaxf(__fadd_rn(__fadd_rn(si, sj.z), -__fmul_rn(2.0f, cv.z)), 0.f), scale);
        lg.w = __fmul_rn(fmaxf(__fadd_rn(__fadd_rn(si, sj.w), -__fmul_rn(2.0f, cv.w)), 0.f), scale);
        *(float4*)&g_D[(size_t)(I + m) * NP + J + n4] = lg;
        if (bi != bj) *(float4*)&sm.u.sC[m * CLD + n4] = lg;
    }

    if (bi != bj) {
        __syncthreads();
        #pragma unroll
        for (int it = 0; it < 16; ++it) {
            int m = tid & 127;
            int g = it * 2 + (tid >> 7);
            float4 vv = *(const float4*)&sm.u.sC[m * CLD + g * 4];
            g_D[(size_t)(J + g * 4 + 0) * NP + I + m] = vv.x;
            g_D[(size_t)(J + g * 4 + 1) * NP + I + m] = vv.y;
            g_D[(size_t)(J + g * 4 + 2) * NP + I + m] = vv.z;
            g_D[(size_t)(J + g * 4 + 3) * NP + I + m] = vv.w;
        }
    }
}

// ============================ select: approx prefilter + EXACT re-evaluation ============================
// Exact logit: sequential-k fma dot of exact X_tilde rows (Xt = d_out), exact
// g_sq, reference op order -> decisions bit-identical to the scalar pipeline.
__device__ __forceinline__ float exact_logit(const float* __restrict__ Xt,
                                             int row, int j, float si, float scale) {
    const float* xi = Xt + (size_t)row * 64;
    const float* xj = Xt + (size_t)j * 64;
    float dot = 0.f;
    #pragma unroll
    for (int kq = 0; kq < 16; ++kq) {
        float4 a = *(const float4*)(xi + kq * 4);   // warp-broadcast (same row)
        float4 bv = __ldg((const float4*)(xj + kq * 4));
        dot = fmaf(a.x, bv.x, dot);
        dot = fmaf(a.y, bv.y, dot);
        dot = fmaf(a.z, bv.z, dot);
        dot = fmaf(a.w, bv.w, dot);
    }
    float d = __fadd_rn(__fadd_rn(si, g_sq[j]), -__fmul_rn(2.0f, dot));
    return __fmul_rn(fmaxf(d, 0.0f), scale);
}

__global__ void __launch_bounds__(128) k_select(
        const float* __restrict__ q, const float* __restrict__ tparam,
        const float* __restrict__ Xt, float* __restrict__ out) {
    const int lane = threadIdx.x & 31;
    const int row = blockIdx.x * 4 + (threadIdx.x >> 5);
    const unsigned FULL = 0xffffffffu;
    const float scale = expf(fminf(fmaxf(tparam[0], -5.f), 5.f));

    const float* Drow = g_D + (size_t)row * NP;
    const float* qrow = q + (size_t)row * NP;
    const float si = g_sq[row];
    unsigned kHi = 0xFF800000u, kLo = 0xFFFFFFFFu;  // +inf sentinel
    float lgS = 0.f;
    float th = __int_as_float(0x7f800000);

    float4 buf[4];
    #pragma unroll
    for (int i = 0; i < 3; ++i)
        buf[i] = *(const float4*)&Drow[(i * 32 + lane) * 4];

    for (int m = 0; m < 64; ++m) {
        if (m + 3 < 64)
            buf[(m + 3) & 3] = *(const float4*)&Drow[((m + 3) * 32 + lane) * 4];
        float4 v = buf[m & 3];

        // conservative bound: gumbel >= -16.64, approx err < 1.0 -> slack 18
        bool p0 = (v.x - 18.0f) <= th;
        bool p1 = (v.y - 18.0f) <= th;
        bool p2 = (v.z - 18.0f) <= th;
        bool p3 = (v.w - 18.0f) <= th;
        unsigned any = __ballot_sync(FULL, p0 | p1 | p2 | p3);
        if (any) {
            // exact re-evaluation for passing elements
            float pe0 = 0.f, pe1 = 0.f, pe2 = 0.f, pe3 = 0.f;
            float lx0 = 0.f, lx1 = 0.f, lx2 = 0.f, lx3 = 0.f;
            int jb = (m * 32 + lane) * 4;
            if (p0 | p1 | p2 | p3) {
                float4 qv = *(const float4*)&qrow[jb];
                if (p0) { lx0 = exact_logit(Xt, row, jb + 0, si, scale);
                          pe0 = __fadd_rn(lx0, logf(-logf(qv.x))); }
                if (p1) { lx1 = exact_logit(Xt, row, jb + 1, si, scale);
                          pe1 = __fadd_rn(lx1, logf(-logf(qv.y))); }
                if (p2) { lx2 = exact_logit(Xt, row, jb + 2, si, scale);
                          pe2 = __fadd_rn(lx2, logf(-logf(qv.z))); }
                if (p3) { lx3 = exact_logit(Xt, row, jb + 3, si, scale);
                          pe3 = __fadd_rn(lx3, logf(-logf(qv.w))); }
            }
            #pragma unroll
            for (int c = 0; c < 4; ++c) {
                float pc = (c == 0) ? pe0 : (c == 1) ? pe1 : (c == 2) ? pe2 : pe3;
                float vc = (c == 0) ? lx0 : (c == 1) ? lx1 : (c == 2) ? lx2 : lx3;
                bool  pp = (c == 0) ? p0 : (c == 1) ? p1 : (c == 2) ? p2 : p3;
                unsigned mc = __ballot_sync(FULL, pp);
                while (mc) {
                    int L = __ffs(mc) - 1; mc &= mc - 1;
                    float np = __shfl_sync(FULL, pc, L);
                    float nl = __shfl_sync(FULL, vc, L);
                    unsigned nk = fenc(np);
                    unsigned nj = (unsigned)((m * 32 + L) * 4 + c);
                    bool le = (kHi < nk) | ((kHi == nk) & (kLo <= nj));
                    int pos = __popc(__ballot_sync(FULL, le));
                    unsigned sHi = __shfl_up_sync(FULL, kHi, 1);
                    unsigned sLo = __shfl_up_sync(FULL, kLo, 1);
                    float    sLg = __shfl_up_sync(FULL, lgS, 1);
                    if (lane == pos)      { kHi = nk;  kLo = nj;  lgS = nl;  }
                    else if (lane > pos)  { kHi = sHi; kLo = sLo; lgS = sLg; }
                }
            }
            th = fdec(__shfl_sync(FULL, kHi, 15));
        }
    }

    if (lane < 16) {
        out[524288 + row * 16 + lane] = (float)kLo;     // edge_index[0]
        out[655360 + row * 16 + lane] = (float)row;     // edge_index[1]
        out[786432 + row * 16 + lane] = -lgS;           // logprobs (exact)
    }
}

extern "C" void kernel_launch(void* const* d_in, const int* in_sizes, int n_in,
                              void* d_out, int out_size) {
    const float* X = (const float*)d_in[0];
    const float* W = (const float*)d_in[1];
    const float* b = (const float*)d_in[2];
    const float* t = (const float*)d_in[3];
    const float* q = (const float*)d_in[4];
    float* out = (float*)d_out;

    k_embed<<<2048, 256>>>(X, W, b, out);
    int smem = (int)sizeof(GW);
    cudaFuncSetAttribute(k_gemm_w, cudaFuncAttributeMaxDynamicSharedMemorySize, smem);
    k_gemm_w<<<NB * (NB + 1) / 2, 256, smem>>>(t);
    k_select<<<2048, 128>>>(q, t, out, out);
}

// round 15
// speedup vs baseline: 1.0433x; 1.0433x over previous
#include <cuda_runtime.h>
#include <cuda_bf16.h>
#include <math.h>
#include <stdint.h>
#include <mma.h>

using namespace nvcuda;

#define NP 8192
#define NB 64

__device__ float g_hi[NP * 64];                 // tf32 high parts
__device__ float g_lo[NP * 64];                 // tf32 low parts
__device__ float g_sq[NP];
__device__ __nv_bfloat16 g_D16[67108864];       // approx logits (prefilter), 134 MB

__device__ __forceinline__ unsigned fenc(float f) {
    unsigned u = __float_as_uint(f);
    return (u & 0x80000000u) ? ~u : (u | 0x80000000u);
}

// ============================ embed (+ tf32 split) ============================
__global__ void __launch_bounds__(256, 1) k_embed(
        const float* __restrict__ X, const float* __restrict__ W,
        const float* __restrict__ b, float* __restrict__ out) {
    __shared__ float s_acc[256];
    int tid = threadIdx.x;
    int row = (blockIdx.x << 2) + (tid >> 6);
    int col = tid & 63;
    const float* xr = X + (size_t)row * 128;
    float acc = 0.f;
    #pragma unroll 16
    for (int k = 0; k < 128; ++k)
        acc = fmaf(__ldg(xr + k), __ldg(W + k * 64 + col), acc);
    acc = __fadd_rn(acc, __ldg(b + col));
    out[row * 64 + col] = acc;           // X_tilde (exact; recheck source)
    float hi_f;
    asm("cvt.rna.tf32.f32 %0, %1;" : "=f"(hi_f) : "f"(acc));
    float rem = __fsub_rn(acc, hi_f);
    float lo_f;
    asm("cvt.rna.tf32.f32 %0, %1;" : "=f"(lo_f) : "f"(rem));
    g_hi[row * 64 + col] = hi_f;
    g_lo[row * 64 + col] = lo_f;
    s_acc[tid] = acc;
    __syncthreads();
    if (tid < 128) {
        int sub = tid >> 5, lane = tid & 31;
        float a = s_acc[sub * 64 + lane];
        float c = s_acc[sub * 64 + 32 + lane];
        float v = a * a + c * c;
        #pragma unroll
        for (int o = 16; o; o >>= 1) v += __shfl_xor_sync(0xffffffffu, v, o);
        if (!lane) g_sq[(blockIdx.x << 2) + sub] = v;
    }
}

// ============================ wmma tf32 3-pass GEMM -> bf16 logits ============================
#define TLD 72
#define CLD 132

struct GW {
    union {
        struct { float Ahi[128 * TLD], Alo[128 * TLD],
                       Bhi[128 * TLD], Blo[128 * TLD]; } t;   // 147.5 KB
        float sC[128 * CLD];                                  // 67.6 KB
    } u;
    float sqi[128], sqj[128];
};

__global__ void __launch_bounds__(256, 1) k_gemm_w(const float* __restrict__ tparam) {
    extern __shared__ char smraw[];
    GW& sm = *reinterpret_cast<GW*>(smraw);
    const int tid = threadIdx.x;
    const int wid = tid >> 5;

    int bidx = blockIdx.x, bi = 0;
    while (bidx >= NB - bi) { bidx -= NB - bi; ++bi; }
    const int bj = bi + bidx;
    const int I = bi * 128, J = bj * 128;
    const float scale = expf(fminf(fmaxf(tparam[0], -5.f), 5.f));

    #pragma unroll
    for (int it = 0; it < 8; ++it) {
        int f = it * 256 + tid;
        int m = f >> 4, kq = f & 15;
        int o = m * TLD + kq * 4;
        *(float4*)&sm.u.t.Ahi[o] = *(const float4*)&g_hi[(size_t)(I + m) * 64 + kq * 4];
        *(float4*)&sm.u.t.Alo[o] = *(const float4*)&g_lo[(size_t)(I + m) * 64 + kq * 4];
        *(float4*)&sm.u.t.Bhi[o] = *(const float4*)&g_hi[(size_t)(J + m) * 64 + kq * 4];
        *(float4*)&sm.u.t.Blo[o] = *(const float4*)&g_lo[(size_t)(J + m) * 64 + kq * 4];
    }
    if (tid < 128) { sm.sqi[tid] = g_sq[I + tid]; sm.sqj[tid] = g_sq[J + tid]; }
    __syncthreads();

    const int wm = (wid & 3) * 32, wn = (wid >> 2) * 64;
    wmma::fragment<wmma::accumulator, 16, 16, 8, float> c[2][4];
    #pragma unroll
    for (int s = 0; s < 2; ++s)
        #pragma unroll
        for (int t = 0; t < 4; ++t) wmma::fill_fragment(c[s][t], 0.0f);

    #pragma unroll
    for (int p = 0; p < 3; ++p) {
        const float* A = (p == 2) ? sm.u.t.Alo : sm.u.t.Ahi;
        const float* B = (p == 1) ? sm.u.t.Blo : sm.u.t.Bhi;
        #pragma unroll
        for (int k8 = 0; k8 < 8; ++k8) {
            wmma::fragment<wmma::matrix_a, 16, 16, 8, wmma::precision::tf32,
                           wmma::row_major> a[2];
            wmma::fragment<wmma::matrix_b, 16, 16, 8, wmma::precision::tf32,
                           wmma::col_major> bf[4];
            #pragma unroll
            for (int s = 0; s < 2; ++s)
                wmma::load_matrix_sync(a[s], &A[(wm + 16 * s) * TLD + k8 * 8], TLD);
            #pragma unroll
            for (int t = 0; t < 4; ++t)
                wmma::load_matrix_sync(bf[t], &B[(wn + 16 * t) * TLD + k8 * 8], TLD);
            #pragma unroll
            for (int s = 0; s < 2; ++s)
                #pragma unroll
                for (int t = 0; t < 4; ++t)
                    wmma::mma_sync(c[s][t], a[s], bf[t], c[s][t]);
        }
    }
    __syncthreads();

    #pragma unroll
    for (int s = 0; s < 2; ++s)
        #pragma unroll
        for (int t = 0; t < 4; ++t)
            wmma::store_matrix_sync(&sm.u.sC[(wm + 16 * s) * CLD + wn + 16 * t],
                                    c[s][t], CLD, wmma::mem_row_major);
    __syncthreads();

    // logits; direct bf16 store; stash f32 in sC for mirror
    #pragma unroll
    for (int it = 0; it < 16; ++it) {
        int f = it * 256 + tid;
        int m = f >> 5, n4 = (f & 31) * 4;
        float4 cv = *(const float4*)&sm.u.sC[m * CLD + n4];
        float si = sm.sqi[m];
        float4 sj = *(const float4*)&sm.sqj[n4];
        float4 lg;
        lg.x = __fmul_rn(fmaxf(__fadd_rn(__fadd_rn(si, sj.x), -__fmul_rn(2.0f, cv.x)), 0.f), scale);
        lg.y = __fmul_rn(fmaxf(__fadd_rn(__fadd_rn(si, sj.y), -__fmul_rn(2.0f, cv.y)), 0.f), scale);
        lg.z = __fmul_rn(fmaxf(__fadd_rn(__fadd_rn(si, sj.z), -__fmul_rn(2.0f, cv.z)), 0.f), scale);
        lg.w = __fmul_rn(fmaxf(__fadd_rn(__fadd_rn(si, sj.w), -__fmul_rn(2.0f, cv.w)), 0.f), scale);
        __nv_bfloat162 b0 = __floats2bfloat162_rn(lg.x, lg.y);
        __nv_bfloat162 b1 = __floats2bfloat162_rn(lg.z, lg.w);
        *(__nv_bfloat162*)&g_D16[(size_t)(I + m) * NP + J + n4]     = b0;
        *(__nv_bfloat162*)&g_D16[(size_t)(I + m) * NP + J + n4 + 2] = b1;
        if (bi != bj) *(float4*)&sm.u.sC[m * CLD + n4] = lg;
    }

    if (bi != bj) {
        __syncthreads();
        #pragma unroll
        for (int it = 0; it < 16; ++it) {
            int m = tid & 127;                  // lanes consecutive m -> coalesced
            int g = it * 2 + (tid >> 7);        // n-quad 0..31
            float4 vv = *(const float4*)&sm.u.sC[m * CLD + g * 4];
            g_D16[(size_t)(J + g * 4 + 0) * NP + I + m] = __float2bfloat16_rn(vv.x);
            g_D16[(size_t)(J + g * 4 + 1) * NP + I + m] = __float2bfloat16_rn(vv.y);
            g_D16[(size_t)(J + g * 4 + 2) * NP + I + m] = __float2bfloat16_rn(vv.z);
            g_D16[(size_t)(J + g * 4 + 3) * NP + I + m] = __float2bfloat16_rn(vv.w);
        }
    }
}

// ============================ fused select: approx pass + exact pass ============================
__device__ __forceinline__ float exact_logit_r(const float4* __restrict__ xi,
                                               const float* __restrict__ Xt,
                                               int j, float si, float scale) {
    const float* xj = Xt + (size_t)j * 64;
    float dot = 0.f;
    #pragma unroll
    for (int kq = 0; kq < 16; ++kq) {
        float4 a = xi[kq];
        float4 bv = __ldg((const float4*)(xj + kq * 4));
        dot = fmaf(a.x, bv.x, dot);
        dot = fmaf(a.y, bv.y, dot);
        dot = fmaf(a.z, bv.z, dot);
        dot = fmaf(a.w, bv.w, dot);
    }
    float d = __fadd_rn(__fadd_rn(si, g_sq[j]), -__fmul_rn(2.0f, dot));
    return __fmul_rn(fmaxf(d, 0.0f), scale);
}

__global__ void __launch_bounds__(128) k_final(
        const float* __restrict__ q, const float* __restrict__ tparam,
        const float* __restrict__ Xt, float* __restrict__ out) {
    const int lane = threadIdx.x & 31;
    const int row = blockIdx.x * 4 + (threadIdx.x >> 5);
    const unsigned FULL = 0xffffffffu;
    const float scale = expf(fminf(fmaxf(tparam[0], -5.f), 5.f));
    const float INFF = __int_as_float(0x7f800000);

    const uint4* Dr = (const uint4*)(g_D16 + (size_t)row * NP);  // 8 bf16 per uint4
    const float* qrow = q + (size_t)row * NP;
    const float si = g_sq[row];

    // ---- phase A: approx top-16 of bf16 logits (value-only distributed list) ----
    float sv = INFF;
    float thA = INFF;
    for (int m = 0; m < 32; ++m) {
        uint4 w = __ldg(Dr + m * 32 + lane);
        float v[8];
        {
            float2 f;
            f = __bfloat1622float2(*(__nv_bfloat162*)&w.x); v[0] = f.x; v[1] = f.y;
            f = __bfloat1622float2(*(__nv_bfloat162*)&w.y); v[2] = f.x; v[3] = f.y;
            f = __bfloat1622float2(*(__nv_bfloat162*)&w.z); v[4] = f.x; v[5] = f.y;
            f = __bfloat1622float2(*(__nv_bfloat162*)&w.w); v[6] = f.x; v[7] = f.y;
        }
        #pragma unroll
        for (int c = 0; c < 8; ++c) {
            unsigned mc = __ballot_sync(FULL, v[c] <= thA);
            while (mc) {
                int L = __ffs(mc) - 1; mc &= mc - 1;
                float nv = __shfl_sync(FULL, v[c], L);
                bool le = (sv <= nv);
                int pos = __popc(__ballot_sync(FULL, le));
                float up = __shfl_up_sync(FULL, sv, 1);
                if (lane == pos)     sv = nv;
                else if (lane > pos) sv = up;
            }
        }
        thA = __shfl_sync(FULL, sv, 15);
    }
    const float T = thA + 60.0f;   // covers gumbel span + 2*(tf32+bf16) error, proven bound

    // ---- phase B: candidates -> EXACT logit + gumbel + exact top-16 ----
    float4 xi[16];
    {
        const float* xr = Xt + (size_t)row * 64;
        #pragma unroll
        for (int kq = 0; kq < 16; ++kq) xi[kq] = *(const float4*)(xr + kq * 4);
    }
    unsigned kHi = 0xFF800000u, kLo = 0xFFFFFFFFu;  // +inf sentinel keys
    float lgS = 0.f;

    for (int m = 0; m < 32; ++m) {
        uint4 w = __ldg(Dr + m * 32 + lane);         // L2-hot re-read
        float v[8];
        {
            float2 f;
            f = __bfloat1622float2(*(__nv_bfloat162*)&w.x); v[0] = f.x; v[1] = f.y;
            f = __bfloat1622float2(*(__nv_bfloat162*)&w.y); v[2] = f.x; v[3] = f.y;
            f = __bfloat1622float2(*(__nv_bfloat162*)&w.z); v[4] = f.x; v[5] = f.y;
            f = __bfloat1622float2(*(__nv_bfloat162*)&w.w); v[6] = f.x; v[7] = f.y;
        }
        #pragma unroll
        for (int c = 0; c < 8; ++c) {
            bool pp = (v[c] <= T);
            float lx = 0.f, pe = 0.f;
            if (pp) {
                int j = m * 256 + lane * 8 + c;
                lx = exact_logit_r(xi, Xt, j, si, scale);
                float qv = __ldg(qrow + j);
                pe = __fadd_rn(lx, logf(-logf(qv)));
            }
            unsigned mc = __ballot_sync(FULL, pp);
            while (mc) {
                int L = __ffs(mc) - 1; mc &= mc - 1;
                float np = __shfl_sync(FULL, pe, L);
                float nl = __shfl_sync(FULL, lx, L);
                unsigned nk = fenc(np);
                unsigned nj = (unsigned)(m * 256 + L * 8 + c);
                bool le = (kHi < nk) | ((kHi == nk) & (kLo <= nj));
                int pos = __popc(__ballot_sync(FULL, le));
                unsigned sHi = __shfl_up_sync(FULL, kHi, 1);
                unsigned sLo = __shfl_up_sync(FULL, kLo, 1);
                float    sLg = __shfl_up_sync(FULL, lgS, 1);
                if (lane == pos)      { kHi = nk;  kLo = nj;  lgS = nl;  }
                else if (lane > pos)  { kHi = sHi; kLo = sLo; lgS = sLg; }
            }
        }
    }

    if (lane < 16) {
        out[524288 + row * 16 + lane] = (float)kLo;     // edge_index[0]
        out[655360 + row * 16 + lane] = (float)row;     // edge_index[1]
        out[786432 + row * 16 + lane] = -lgS;           // logprobs (exact)
    }
}

extern "C" void kernel_launch(void* const* d_in, const int* in_sizes, int n_in,
                              void* d_out, int out_size) {
    const float* X = (const float*)d_in[0];
    const float* W = (const float*)d_in[1];
    const float* b = (const float*)d_in[2];
    const float* t = (const float*)d_in[3];
    const float* q = (const float*)d_in[4];
    float* out = (float*)d_out;

    k_embed<<<2048, 256>>>(X, W, b, out);
    int smem = (int)sizeof(GW);
    cudaFuncSetAttribute(k_gemm_w, cudaFuncAttributeMaxDynamicSharedMemorySize, smem);
    k_gemm_w<<<NB * (NB + 1) / 2, 256, smem>>>(t);
    k_final<<<2048, 128>>>(q, t, out, out);
}

// round 16
// speedup vs baseline: 1.2326x; 1.1814x over previous
#include <cuda_runtime.h>
#include <cuda_bf16.h>
#include <math.h>
#include <stdint.h>

#define NP 8192
#define NB 64

__device__ float g_xtT[64 * NP];            // [k][i] transposed embeddings
__device__ float g_sq[NP];
__device__ __nv_bfloat16 g_D16[67108864];   // bf16 logits (prefilter), 134 MB

__device__ __forceinline__ unsigned fenc(float f) {
    unsigned u = __float_as_uint(f);
    return (u & 0x80000000u) ? ~u : (u | 0x80000000u);
}

// ============================ embed ============================
__global__ void __launch_bounds__(256, 1) k_embed(
        const float* __restrict__ X, const float* __restrict__ W,
        const float* __restrict__ b, float* __restrict__ out) {
    __shared__ float s_acc[256];
    int tid = threadIdx.x;
    int row = (blockIdx.x << 2) + (tid >> 6);
    int col = tid & 63;
    const float* xr = X + (size_t)row * 128;
    float acc = 0.f;
    #pragma unroll 16
    for (int k = 0; k < 128; ++k)
        acc = fmaf(__ldg(xr + k), __ldg(W + k * 64 + col), acc);
    acc = __fadd_rn(acc, __ldg(b + col));
    out[row * 64 + col] = acc;           // X_tilde (exact; recheck source)
    g_xtT[col * NP + row] = acc;         // transposed copy for GEMM
    s_acc[tid] = acc;
    __syncthreads();
    if (tid < 128) {
        int sub = tid >> 5, lane = tid & 31;
        float a = s_acc[sub * 64 + lane];
        float c = s_acc[sub * 64 + 32 + lane];
        float v = a * a + c * c;
        #pragma unroll
        for (int o = 16; o; o >>= 1) v += __shfl_xor_sync(0xffffffffu, v, o);
        if (!lane) g_sq[(blockIdx.x << 2) + sub] = v;
    }
}

// ============================ scalar exact GEMM -> bf16 logits ============================
struct GU {
    union {
        struct { float sA[64 * 132]; float sB[64 * 132]; } ab;
        float sC[128 * 128];
    };
    float sqi[128];
    float sqj[128];
};

__global__ void __launch_bounds__(256, 2) k_gemm(const float* __restrict__ tparam) {
    extern __shared__ char smraw[];
    GU& sm = *reinterpret_cast<GU*>(smraw);
    const int tid = threadIdx.x;

    // triangular block decode: bi <= bj
    int bidx = blockIdx.x, bi = 0;
    while (bidx >= NB - bi) { bidx -= NB - bi; ++bi; }
    const int bj = bi + bidx;
    const int I = bi * 128, J = bj * 128;
    const float scale = expf(fminf(fmaxf(tparam[0], -5.f), 5.f));
    const int ti = tid >> 4, tj = tid & 15;

    #pragma unroll
    for (int it = 0; it < 8; ++it) {
        int f = it * 256 + tid;
        int k = f >> 5, i4 = f & 31;
        *(float4*)&sm.ab.sA[k * 132 + i4 * 4] =
            *(const float4*)&g_xtT[k * NP + I + i4 * 4];
        *(float4*)&sm.ab.sB[k * 132 + i4 * 4] =
            *(const float4*)&g_xtT[k * NP + J + i4 * 4];
    }
    if (tid < 128) { sm.sqi[tid] = g_sq[I + tid]; sm.sqj[tid] = g_sq[J + tid]; }
    __syncthreads();

    float acc[8][8];
    #pragma unroll
    for (int u = 0; u < 8; ++u)
        #pragma unroll
        for (int v = 0; v < 8; ++v) acc[u][v] = 0.f;

    #pragma unroll 4
    for (int k = 0; k < 64; ++k) {
        float4 a0 = *(const float4*)&sm.ab.sA[k * 132 + ti * 4];
        float4 a1 = *(const float4*)&sm.ab.sA[k * 132 + 64 + ti * 4];
        float4 b0 = *(const float4*)&sm.ab.sB[k * 132 + tj * 4];
        float4 b1 = *(const float4*)&sm.ab.sB[k * 132 + 64 + tj * 4];
        float av[8] = {a0.x, a0.y, a0.z, a0.w, a1.x, a1.y, a1.z, a1.w};
        float bv[8] = {b0.x, b0.y, b0.z, b0.w, b1.x, b1.y, b1.z, b1.w};
        #pragma unroll
        for (int u = 0; u < 8; ++u)
            #pragma unroll
            for (int v = 0; v < 8; ++v)
                acc[u][v] = fmaf(av[u], bv[v], acc[u][v]);
    }

    // epilogue: logits in-place (exact op order, same as the 295us baseline)
    float si[8], sj[8];
    #pragma unroll
    for (int u = 0; u < 8; ++u)
        si[u] = sm.sqi[(u < 4) ? ti * 4 + u : 64 + ti * 4 + (u - 4)];
    #pragma unroll
    for (int v = 0; v < 8; ++v)
        sj[v] = sm.sqj[(v < 4) ? tj * 4 + v : 64 + tj * 4 + (v - 4)];
    #pragma unroll
    for (int u = 0; u < 8; ++u)
        #pragma unroll
        for (int v = 0; v < 8; ++v) {
            float d = __fadd_rn(__fadd_rn(si[u], sj[v]),
                                -__fmul_rn(2.0f, acc[u][v]));
            acc[u][v] = __fmul_rn(fmaxf(d, 0.0f), scale);
        }

    // direct store as bf16 (8 bf16 = two 8-byte stores per u)
    #pragma unroll
    for (int u = 0; u < 8; ++u) {
        int gi = I + ((u < 4) ? ti * 4 + u : 64 + ti * 4 + (u - 4));
        __nv_bfloat162 p0 = __floats2bfloat162_rn(acc[u][0], acc[u][1]);
        __nv_bfloat162 p1 = __floats2bfloat162_rn(acc[u][2], acc[u][3]);
        __nv_bfloat162 p2 = __floats2bfloat162_rn(acc[u][4], acc[u][5]);
        __nv_bfloat162 p3 = __floats2bfloat162_rn(acc[u][6], acc[u][7]);
        *(uint2*)&g_D16[(size_t)gi * NP + J + tj * 4] =
            make_uint2(*(unsigned*)&p0, *(unsigned*)&p1);
        *(uint2*)&g_D16[(size_t)gi * NP + J + 64 + tj * 4] =
            make_uint2(*(unsigned*)&p2, *(unsigned*)&p3);
    }

    if (bi != bj) {
        // transposed store via swizzled smem stage (same f32 -> same bf16: symmetric)
        __syncthreads();
        #pragma unroll
        for (int v = 0; v < 8; ++v) {
            int jl = (v < 4) ? tj * 4 + v : 64 + tj * 4 + (v - 4);
            int sw = ((jl >> 2) & 7) << 2;
            *(float4*)&sm.sC[jl * 128 + ((ti * 4) ^ sw)] =
                make_float4(acc[0][v], acc[1][v], acc[2][v], acc[3][v]);
            *(float4*)&sm.sC[jl * 128 + (64 + ((ti * 4) ^ sw))] =
                make_float4(acc[4][v], acc[5][v], acc[6][v], acc[7][v]);
        }
        __syncthreads();
        #pragma unroll
        for (int it = 0; it < 16; ++it) {
            int f = it * 256 + tid;
            int jl = f >> 5, i4 = f & 31;
            int sw = ((jl >> 2) & 7) << 2;
            int off = i4 * 4;
            int phys = (off < 64) ? (off ^ sw) : (64 + ((off - 64) ^ sw));
            float4 vv = *(const float4*)&sm.sC[jl * 128 + phys];
            __nv_bfloat162 p0 = __floats2bfloat162_rn(vv.x, vv.y);
            __nv_bfloat162 p1 = __floats2bfloat162_rn(vv.z, vv.w);
            *(uint2*)&g_D16[(size_t)(J + jl) * NP + I + i4 * 4] =
                make_uint2(*(unsigned*)&p0, *(unsigned*)&p1);
        }
    }
}

// ============================ fused select: approx pass + exact pass ============================
__device__ __forceinline__ float exact_logit_r(const float4* __restrict__ xi,
                                               const float* __restrict__ Xt,
                                               int j, float si, float scale) {
    const float* xj = Xt + (size_t)j * 64;
    float dot = 0.f;
    #pragma unroll
    for (int kq = 0; kq < 16; ++kq) {
        float4 a = xi[kq];
        float4 bv = __ldg((const float4*)(xj + kq * 4));
        dot = fmaf(a.x, bv.x, dot);
        dot = fmaf(a.y, bv.y, dot);
        dot = fmaf(a.z, bv.z, dot);
        dot = fmaf(a.w, bv.w, dot);
    }
    float d = __fadd_rn(__fadd_rn(si, g_sq[j]), -__fmul_rn(2.0f, dot));
    return __fmul_rn(fmaxf(d, 0.0f), scale);
}

__global__ void __launch_bounds__(128) k_final(
        const float* __restrict__ q, const float* __restrict__ tparam,
        const float* __restrict__ Xt, float* __restrict__ out) {
    const int lane = threadIdx.x & 31;
    const int row = blockIdx.x * 4 + (threadIdx.x >> 5);
    const unsigned FULL = 0xffffffffu;
    const float scale = expf(fminf(fmaxf(tparam[0], -5.f), 5.f));
    const float INFF = __int_as_float(0x7f800000);

    const uint4* Dr = (const uint4*)(g_D16 + (size_t)row * NP);  // 8 bf16 per uint4
    const float* qrow = q + (size_t)row * NP;
    const float si = g_sq[row];

    // ---- phase A: approx top-16 of bf16 logits (value-only distributed list) ----
    float sv = INFF;
    float thA = INFF;
    for (int m = 0; m < 32; ++m) {
        uint4 w = __ldg(Dr + m * 32 + lane);
        float v[8];
        {
            float2 f;
            f = __bfloat1622float2(*(__nv_bfloat162*)&w.x); v[0] = f.x; v[1] = f.y;
            f = __bfloat1622float2(*(__nv_bfloat162*)&w.y); v[2] = f.x; v[3] = f.y;
            f = __bfloat1622float2(*(__nv_bfloat162*)&w.z); v[4] = f.x; v[5] = f.y;
            f = __bfloat1622float2(*(__nv_bfloat162*)&w.w); v[6] = f.x; v[7] = f.y;
        }
        #pragma unroll
        for (int c = 0; c < 8; ++c) {
            unsigned mc = __ballot_sync(FULL, v[c] <= thA);
            while (mc) {
                int L = __ffs(mc) - 1; mc &= mc - 1;
                float nv = __shfl_sync(FULL, v[c], L);
                bool le = (sv <= nv);
                int pos = __popc(__ballot_sync(FULL, le));
                float up = __shfl_up_sync(FULL, sv, 1);
                if (lane == pos)     sv = nv;
                else if (lane > pos) sv = up;
            }
        }
        thA = __shfl_sync(FULL, sv, 15);
    }
    // bound: gumbel span 19.7 + 2*bf16_err (<=16 each) = 51.7 -> slack 60
    const float T = thA + 60.0f;

    // ---- phase B: candidates -> EXACT logit + gumbel + exact top-16 ----
    float4 xi[16];
    {
        const float* xr = Xt + (size_t)row * 64;
        #pragma unroll
        for (int kq = 0; kq < 16; ++kq) xi[kq] = *(const float4*)(xr + kq * 4);
    }
    unsigned kHi = 0xFF800000u, kLo = 0xFFFFFFFFu;  // +inf sentinel keys
    float lgS = 0.f;

    for (int m = 0; m < 32; ++m) {
        uint4 w = __ldg(Dr + m * 32 + lane);         // L2-warm re-read
        float v[8];
        {
            float2 f;
            f = __bfloat1622float2(*(__nv_bfloat162*)&w.x); v[0] = f.x; v[1] = f.y;
            f = __bfloat1622float2(*(__nv_bfloat162*)&w.y); v[2] = f.x; v[3] = f.y;
            f = __bfloat1622float2(*(__nv_bfloat162*)&w.z); v[4] = f.x; v[5] = f.y;
            f = __bfloat1622float2(*(__nv_bfloat162*)&w.w); v[6] = f.x; v[7] = f.y;
        }
        #pragma unroll
        for (int c = 0; c < 8; ++c) {
            bool pp = (v[c] <= T);
            float lx = 0.f, pe = 0.f;
            if (pp) {
                int j = m * 256 + lane * 8 + c;
                lx = exact_logit_r(xi, Xt, j, si, scale);
                float qv = __ldg(qrow + j);
                pe = __fadd_rn(lx, logf(-logf(qv)));
            }
            unsigned mc = __ballot_sync(FULL, pp);
            while (mc) {
                int L = __ffs(mc) - 1; mc &= mc - 1;
                float np = __shfl_sync(FULL, pe, L);
                float nl = __shfl_sync(FULL, lx, L);
                unsigned nk = fenc(np);
                unsigned nj = (unsigned)(m * 256 + L * 8 + c);
                bool le = (kHi < nk) | ((kHi == nk) & (kLo <= nj));
                int pos = __popc(__ballot_sync(FULL, le));
                unsigned sHi = __shfl_up_sync(FULL, kHi, 1);
                unsigned sLo = __shfl_up_sync(FULL, kLo, 1);
                float    sLg = __shfl_up_sync(FULL, lgS, 1);
                if (lane == pos)      { kHi = nk;  kLo = nj;  lgS = nl;  }
                else if (lane > pos)  { kHi = sHi; kLo = sLo; lgS = sLg; }
            }
        }
    }

    if (lane < 16) {
        out[524288 + row * 16 + lane] = (float)kLo;     // edge_index[0]
        out[655360 + row * 16 + lane] = (float)row;     // edge_index[1]
        out[786432 + row * 16 + lane] = -lgS;           // logprobs (exact)
    }
}

extern "C" void kernel_launch(void* const* d_in, const int* in_sizes, int n_in,
                              void* d_out, int out_size) {
    const float* X = (const float*)d_in[0];
    const float* W = (const float*)d_in[1];
    const float* b = (const float*)d_in[2];
    const float* t = (const float*)d_in[3];
    const float* q = (const float*)d_in[4];
    float* out = (float*)d_out;

    k_embed<<<2048, 256>>>(X, W, b, out);
    int smem = (int)sizeof(GU);
    cudaFuncSetAttribute(k_gemm, cudaFuncAttributeMaxDynamicSharedMemorySize, smem);
    k_gemm<<<NB * (NB + 1) / 2, 256, smem>>>(t);
    k_final<<<2048, 128>>>(q, t, out, out);
}

// round 17
// speedup vs baseline: 2.0829x; 1.6898x over previous
#include <cuda_runtime.h>
#include <math.h>

#define NP 8192
#define NB 64   // number of 128-wide blocks

__device__ float g_xtT[64 * NP];            // [k][i] transposed embeddings
__device__ float g_sq[NP];
__device__ float g_D[67108864];             // logits matrix, 256 MB

__device__ __forceinline__ unsigned fenc(float f) {
    unsigned u = __float_as_uint(f);
    return (u & 0x80000000u) ? ~u : (u | 0x80000000u);
}
__device__ __forceinline__ float fdec(unsigned k) {
    return (k & 0x80000000u) ? __uint_as_float(k ^ 0x80000000u)
                             : __uint_as_float(~k);
}

// ============================ embed ============================
__global__ void __launch_bounds__(256, 1) k_embed(
        const float* __restrict__ X, const float* __restrict__ W,
        const float* __restrict__ b, float* __restrict__ out) {
    __shared__ float s_acc[256];
    int tid = threadIdx.x;
    int row = (blockIdx.x << 2) + (tid >> 6);
    int col = tid & 63;
    const float* xr = X + (size_t)row * 128;
    float acc = 0.f;
    #pragma unroll 16
    for (int k = 0; k < 128; ++k)
        acc = fmaf(__ldg(xr + k), __ldg(W + k * 64 + col), acc);
    acc = __fadd_rn(acc, __ldg(b + col));
    out[row * 64 + col] = acc;           // X_tilde output
    g_xtT[col * NP + row] = acc;         // transposed copy for GEMM
    s_acc[tid] = acc;
    __syncthreads();
    if (tid < 128) {
        int sub = tid >> 5, lane = tid & 31;
        float a = s_acc[sub * 64 + lane];
        float c = s_acc[sub * 64 + 32 + lane];
        float v = a * a + c * c;
        #pragma unroll
        for (int o = 16; o; o >>= 1) v += __shfl_xor_sync(0xffffffffu, v, o);
        if (!lane) g_sq[(blockIdx.x << 2) + sub] = v;
    }
}

// ============================ gemm -> logits matrix (exact f32) ============================
struct GU {
    union {
        struct { float sA[64 * 132]; float sB[64 * 132]; } ab;
        float sC[128 * 128];
    };
    float sqi[128];
    float sqj[128];
};

__global__ void __launch_bounds__(256, 2) k_gemm(const float* __restrict__ tparam) {
    extern __shared__ char smraw[];
    GU& sm = *reinterpret_cast<GU*>(smraw);
    const int tid = threadIdx.x;

    // triangular block decode: bi <= bj
    int bidx = blockIdx.x, bi = 0;
    while (bidx >= NB - bi) { bidx -= NB - bi; ++bi; }
    const int bj = bi + bidx;
    const int I = bi * 128, J = bj * 128;
    const float scale = expf(fminf(fmaxf(tparam[0], -5.f), 5.f));
    const int ti = tid >> 4, tj = tid & 15;

    #pragma unroll
    for (int it = 0; it < 8; ++it) {
        int f = it * 256 + tid;
        int k = f >> 5, i4 = f & 31;
        *(float4*)&sm.ab.sA[k * 132 + i4 * 4] =
            *(const float4*)&g_xtT[k * NP + I + i4 * 4];
        *(float4*)&sm.ab.sB[k * 132 + i4 * 4] =
            *(const float4*)&g_xtT[k * NP + J + i4 * 4];
    }
    if (tid < 128) { sm.sqi[tid] = g_sq[I + tid]; sm.sqj[tid] = g_sq[J + tid]; }
    __syncthreads();

    float acc[8][8];
    #pragma unroll
    for (int u = 0; u < 8; ++u)
        #pragma unroll
        for (int v = 0; v < 8; ++v) acc[u][v] = 0.f;

    #pragma unroll 4
    for (int k = 0; k < 64; ++k) {
        float4 a0 = *(const float4*)&sm.ab.sA[k * 132 + ti * 4];
        float4 a1 = *(const float4*)&sm.ab.sA[k * 132 + 64 + ti * 4];
        float4 b0 = *(const float4*)&sm.ab.sB[k * 132 + tj * 4];
        float4 b1 = *(const float4*)&sm.ab.sB[k * 132 + 64 + tj * 4];
        float av[8] = {a0.x, a0.y, a0.z, a0.w, a1.x, a1.y, a1.z, a1.w};
        float bv[8] = {b0.x, b0.y, b0.z, b0.w, b1.x, b1.y, b1.z, b1.w};
        #pragma unroll
        for (int u = 0; u < 8; ++u)
            #pragma unroll
            for (int v = 0; v < 8; ++v)
                acc[u][v] = fmaf(av[u], bv[v], acc[u][v]);
    }

    // epilogue: logits in-place (exact reference op order)
    float si[8], sj[8];
    #pragma unroll
    for (int u = 0; u < 8; ++u)
        si[u] = sm.sqi[(u < 4) ? ti * 4 + u : 64 + ti * 4 + (u - 4)];
    #pragma unroll
    for (int v = 0; v < 8; ++v)
        sj[v] = sm.sqj[(v < 4) ? tj * 4 + v : 64 + tj * 4 + (v - 4)];
    #pragma unroll
    for (int u = 0; u < 8; ++u)
        #pragma unroll
        for (int v = 0; v < 8; ++v) {
            float d = __fadd_rn(__fadd_rn(si[u], sj[v]),
                                -__fmul_rn(2.0f, acc[u][v]));
            acc[u][v] = __fmul_rn(fmaxf(d, 0.0f), scale);
        }

    // direct store: block (bi rows, bj cols)
    #pragma unroll
    for (int u = 0; u < 8; ++u) {
        int gi = I + ((u < 4) ? ti * 4 + u : 64 + ti * 4 + (u - 4));
        *(float4*)&g_D[(size_t)gi * NP + J + tj * 4] =
            make_float4(acc[u][0], acc[u][1], acc[u][2], acc[u][3]);
        *(float4*)&g_D[(size_t)gi * NP + J + 64 + tj * 4] =
            make_float4(acc[u][4], acc[u][5], acc[u][6], acc[u][7]);
    }

    if (bi != bj) {
        // transposed store via swizzled smem stage (bit-identical by symmetry)
        __syncthreads();
        #pragma unroll
        for (int v = 0; v < 8; ++v) {
            int jl = (v < 4) ? tj * 4 + v : 64 + tj * 4 + (v - 4);
            int sw = ((jl >> 2) & 7) << 2;
            *(float4*)&sm.sC[jl * 128 + ((ti * 4) ^ sw)] =
                make_float4(acc[0][v], acc[1][v], acc[2][v], acc[3][v]);
            *(float4*)&sm.sC[jl * 128 + (64 + ((ti * 4) ^ sw))] =
                make_float4(acc[4][v], acc[5][v], acc[6][v], acc[7][v]);
        }
        __syncthreads();
        #pragma unroll
        for (int it = 0; it < 16; ++it) {
            int f = it * 256 + tid;
            int jl = f >> 5, i4 = f & 31;
            int sw = ((jl >> 2) & 7) << 2;
            int off = i4 * 4;
            int phys = (off < 64) ? (off ^ sw) : (64 + ((off - 64) ^ sw));
            float4 vv = *(const float4*)&sm.sC[jl * 128 + phys];
            *(float4*)&g_D[(size_t)(J + jl) * NP + I + i4 * 4] = vv;
        }
    }
}

// ============================ select: warp-per-row exact top-16, 4-deep pipeline ============================
__global__ void __launch_bounds__(128) k_select(
        const float* __restrict__ q, float* __restrict__ out) {
    const int lane = threadIdx.x & 31;
    const int row = blockIdx.x * 4 + (threadIdx.x >> 5);
    const unsigned FULL = 0xffffffffu;

    const float* Drow = g_D + (size_t)row * NP;
    const float* qrow = q + (size_t)row * NP;
    // distributed sorted list: slot `lane` (lanes 0..15 are the answer)
    unsigned kHi = 0xFF800000u, kLo = 0xFFFFFFFFu;  // +inf sentinel
    float lgS = 0.f;
    float th = __int_as_float(0x7f800000);

    float4 buf[4];
    #pragma unroll
    for (int i = 0; i < 3; ++i)
        buf[i] = *(const float4*)&Drow[(i * 32 + lane) * 4];

    for (int m = 0; m < 64; ++m) {
        if (m + 3 < 64)
            buf[(m + 3) & 3] = *(const float4*)&Drow[((m + 3) * 32 + lane) * 4];
        float4 v = buf[m & 3];

        bool p0 = (v.x - 17.0f) <= th;   // gumbel in [-2.92,16.64] -> exact bound
        bool p1 = (v.y - 17.0f) <= th;
        bool p2 = (v.z - 17.0f) <= th;
        bool p3 = (v.w - 17.0f) <= th;
        unsigned any = __ballot_sync(FULL, p0 | p1 | p2 | p3);
        if (any) {
            float pe0 = 0.f, pe1 = 0.f, pe2 = 0.f, pe3 = 0.f;
            if (p0 | p1 | p2 | p3) {
                float4 qv = *(const float4*)&qrow[(m * 32 + lane) * 4];
                if (p0) pe0 = __fadd_rn(v.x, logf(-logf(qv.x)));
                if (p1) pe1 = __fadd_rn(v.y, logf(-logf(qv.y)));
                if (p2) pe2 = __fadd_rn(v.z, logf(-logf(qv.z)));
                if (p3) pe3 = __fadd_rn(v.w, logf(-logf(qv.w)));
            }
            #pragma unroll
            for (int c = 0; c < 4; ++c) {
                float pc = (c == 0) ? pe0 : (c == 1) ? pe1 : (c == 2) ? pe2 : pe3;
                float vc = (c == 0) ? v.x : (c == 1) ? v.y : (c == 2) ? v.z : v.w;
                bool  pp = (c == 0) ? p0 : (c == 1) ? p1 : (c == 2) ? p2 : p3;
                unsigned mc = __ballot_sync(FULL, pp);
                while (mc) {
                    int L = __ffs(mc) - 1; mc &= mc - 1;
                    float np = __shfl_sync(FULL, pc, L);
                    float nl = __shfl_sync(FULL, vc, L);
                    unsigned nk = fenc(np);
                    unsigned nj = (unsigned)((m * 32 + L) * 4 + c);
                    bool le = (kHi < nk) | ((kHi == nk) & (kLo <= nj));
                    int pos = __popc(__ballot_sync(FULL, le));
                    unsigned sHi = __shfl_up_sync(FULL, kHi, 1);
                    unsigned sLo = __shfl_up_sync(FULL, kLo, 1);
                    float    sLg = __shfl_up_sync(FULL, lgS, 1);
                    if (lane == pos)      { kHi = nk;  kLo = nj;  lgS = nl;  }
                    else if (lane > pos)  { kHi = sHi; kLo = sLo; lgS = sLg; }
                }
            }
            th = fdec(__shfl_sync(FULL, kHi, 15));
        }
    }

    if (lane < 16) {
        out[524288 + row * 16 + lane] = (float)kLo;     // edge_index[0]
        out[655360 + row * 16 + lane] = (float)row;     // edge_index[1]
        out[786432 + row * 16 + lane] = -lgS;           // logprobs
    }
}

extern "C" void kernel_launch(void* const* d_in, const int* in_sizes, int n_in,
                              void* d_out, int out_size) {
    const float* X = (const float*)d_in[0];
    const float* W = (const float*)d_in[1];
    const float* b = (const float*)d_in[2];
    const float* t = (const float*)d_in[3];
    const float* q = (const float*)d_in[4];
    float* out = (float*)d_out;

    k_embed<<<2048, 256>>>(X, W, b, out);
    int smem = (int)sizeof(GU);
    cudaFuncSetAttribute(k_gemm, cudaFuncAttributeMaxDynamicSharedMemorySize, smem);
    k_gemm<<<NB * (NB + 1) / 2, 256, smem>>>(t);
    k_select<<<2048, 128>>>(q, out);
}